// round 1
// baseline (speedup 1.0000x reference)
#include <cuda_runtime.h>
#include <math.h>

#define NB 4
#define KB 2
#define DB 2
#define KI 6
#define DI 5
#define ACCB (KB*(DB+1))   /* 6  */
#define ACCI (KI*(DI+1))   /* 36 */
#define TWO_DELTA_D 6.0f
#define DELTA_V 0.5f
#define PARAM_REG 0.001f

// ---------------- scratch (device globals; no allocation allowed) -----------
__device__ float g_bin_acc [NB][ACCB];       // per batch: [k]{sum_d0,sum_d1,count}
__device__ float g_inst_acc[NB][ACCI];       // per batch: [k]{sum_d0..4,count}
__device__ float g_bin_var [NB][KB];
__device__ float g_inst_var[NB][KI];
__device__ float g_bin_mean [NB][KB][DB];
__device__ float g_inst_mean[NB][KI][DI];
__device__ float g_bin_rest [NB];            // l_dist + 0.001*l_reg per batch
__device__ float g_inst_rest[NB];
__device__ int   g_is64[2];                  // [0]=binary labels, [1]=instance labels

__device__ __forceinline__ float f4c(const float4& v, int p) {
    return p == 0 ? v.x : (p == 1 ? v.y : (p == 2 ? v.z : v.w));
}

// ---------------- kernel 0: zero scratch + detect label dtype ---------------
__global__ void zero_detect_kernel(const int* __restrict__ binlab,
                                   const int* __restrict__ instlab) {
    int t = threadIdx.x;
    float* pb = &g_bin_acc[0][0];
    for (int j = t; j < NB*ACCB; j += blockDim.x) pb[j] = 0.f;
    float* pi = &g_inst_acc[0][0];
    for (int j = t; j < NB*ACCI; j += blockDim.x) pi[j] = 0.f;
    float* vb = &g_bin_var[0][0];
    for (int j = t; j < NB*KB; j += blockDim.x) vb[j] = 0.f;
    float* vi = &g_inst_var[0][0];
    for (int j = t; j < NB*KI; j += blockDim.x) vi[j] = 0.f;
    if (t == 0) {
        // If labels are int64 (little-endian), every odd 32-bit word of the
        // first 64 elements is 0. If int32, odd words are random labels:
        // P(all zero) <= 2^-64.
        int b64 = 1, i64 = 1;
        for (int j = 0; j < 64; j++) {
            if (binlab [2*j + 1] != 0) b64 = 0;
            if (instlab[2*j + 1] != 0) i64 = 0;
        }
        g_is64[0] = b64;
        g_is64[1] = i64;
    }
}

// ---------------- pass 1: per-(batch,label) sums + counts -------------------
template<int K, int D>
__global__ __launch_bounds__(256)
void pass1_kernel(const float* __restrict__ logits,
                  const void*  __restrict__ labels,
                  float* __restrict__ gacc,     // [NB][K*(D+1)]
                  int labsel, int MN) {
    constexpr int ACC = K*(D+1);
    const int b = blockIdx.y;
    const float* base = logits + (size_t)b * D * MN;
    const int is64 = g_is64[labsel];
    const int nvec = MN >> 2;

    float acc[ACC];
#pragma unroll
    for (int j = 0; j < ACC; j++) acc[j] = 0.f;

    for (int i = blockIdx.x*blockDim.x + threadIdx.x; i < nvec;
         i += gridDim.x*blockDim.x) {
        float4 x[D];
#pragma unroll
        for (int d = 0; d < D; d++)
            x[d] = ((const float4*)(base + (size_t)d*MN))[i];
        int lab[4];
        if (is64) {
            const longlong4 v = ((const longlong4*)labels)[(size_t)b*nvec + i];
            lab[0]=(int)v.x; lab[1]=(int)v.y; lab[2]=(int)v.z; lab[3]=(int)v.w;
        } else {
            const int4 v = ((const int4*)labels)[(size_t)b*nvec + i];
            lab[0]=v.x; lab[1]=v.y; lab[2]=v.z; lab[3]=v.w;
        }
#pragma unroll
        for (int p = 0; p < 4; p++) {
#pragma unroll
            for (int k = 0; k < K; k++) {
                float m = (lab[p] == k) ? 1.0f : 0.0f;
#pragma unroll
                for (int d = 0; d < D; d++)
                    acc[k*(D+1)+d] = fmaf(m, f4c(x[d], p), acc[k*(D+1)+d]);
                acc[k*(D+1)+D] += m;
            }
        }
    }

    // warp reduce -> smem -> one global atomic per accumulator per block
#pragma unroll
    for (int j = 0; j < ACC; j++) {
        float v = acc[j];
#pragma unroll
        for (int o = 16; o; o >>= 1) v += __shfl_xor_sync(0xffffffffu, v, o);
        acc[j] = v;
    }
    __shared__ float red[ACC];
    if (threadIdx.x < ACC) red[threadIdx.x] = 0.f;
    __syncthreads();
    if ((threadIdx.x & 31) == 0) {
#pragma unroll
        for (int j = 0; j < ACC; j++) atomicAdd(&red[j], acc[j]);
    }
    __syncthreads();
    if (threadIdx.x < ACC) atomicAdd(&gacc[b*ACC + threadIdx.x], red[threadIdx.x]);
}

// ---------------- mid: means + push/reg terms (tiny) ------------------------
__global__ void mid_kernel() {
    int t = threadIdx.x;
    if (t < NB*KB) {
        int b = t / KB, k = t % KB;
        float c = g_bin_acc[b][k*(DB+1)+DB];
        for (int d = 0; d < DB; d++)
            g_bin_mean[b][k][d] = g_bin_acc[b][k*(DB+1)+d] / c;
    }
    if (t < NB*KI) {
        int b = t / KI, k = t % KI;
        float c = g_inst_acc[b][k*(DI+1)+DI];
        for (int d = 0; d < DI; d++)
            g_inst_mean[b][k][d] = g_inst_acc[b][k*(DI+1)+d] / c;
    }
    __syncthreads();
    if (t < NB) {
        int b = t;
        float ld = 0.f;
        for (int i = 0; i < KB; i++)
            for (int j = 0; j < KB; j++) if (i != j) {
                float s = 0.f;
                for (int d = 0; d < DB; d++) {
                    float df = g_bin_mean[b][i][d] - g_bin_mean[b][j][d];
                    s += df*df;
                }
                float dn = fmaxf(TWO_DELTA_D - sqrtf(s), 0.f);
                ld += dn*dn;
            }
        ld /= (float)(KB*(KB-1));
        float lr = 0.f;
        for (int k = 0; k < KB; k++) {
            float s = 0.f;
            for (int d = 0; d < DB; d++) s += g_bin_mean[b][k][d]*g_bin_mean[b][k][d];
            lr += sqrtf(s);
        }
        lr /= (float)KB;
        g_bin_rest[b] = ld + PARAM_REG * lr;
    } else if (t < 2*NB) {
        int b = t - NB;
        float ld = 0.f;
        for (int i = 0; i < KI; i++)
            for (int j = 0; j < KI; j++) if (i != j) {
                float s = 0.f;
                for (int d = 0; d < DI; d++) {
                    float df = g_inst_mean[b][i][d] - g_inst_mean[b][j][d];
                    s += df*df;
                }
                float dn = fmaxf(TWO_DELTA_D - sqrtf(s), 0.f);
                ld += dn*dn;
            }
        ld /= (float)(KI*(KI-1));
        float lr = 0.f;
        for (int k = 0; k < KI; k++) {
            float s = 0.f;
            for (int d = 0; d < DI; d++) s += g_inst_mean[b][k][d]*g_inst_mean[b][k][d];
            lr += sqrtf(s);
        }
        lr /= (float)KI;
        g_inst_rest[b] = ld + PARAM_REG * lr;
    }
}

// ---------------- pass 2: hinge variance sums -------------------------------
template<int K, int D>
__global__ __launch_bounds__(256)
void pass2_kernel(const float* __restrict__ logits,
                  const void*  __restrict__ labels,
                  const float* __restrict__ gmean,   // [NB][K][D]
                  float* __restrict__ gvar,          // [NB][K]
                  int labsel, int MN) {
    const int b = blockIdx.y;
    const float* base = logits + (size_t)b * D * MN;
    const int is64 = g_is64[labsel];
    const int nvec = MN >> 2;

    float mean[K][D];
#pragma unroll
    for (int k = 0; k < K; k++)
#pragma unroll
        for (int d = 0; d < D; d++)
            mean[k][d] = gmean[((size_t)b*K + k)*D + d];

    float accv[K];
#pragma unroll
    for (int k = 0; k < K; k++) accv[k] = 0.f;

    for (int i = blockIdx.x*blockDim.x + threadIdx.x; i < nvec;
         i += gridDim.x*blockDim.x) {
        float4 x[D];
#pragma unroll
        for (int d = 0; d < D; d++)
            x[d] = ((const float4*)(base + (size_t)d*MN))[i];
        int lab[4];
        if (is64) {
            const longlong4 v = ((const longlong4*)labels)[(size_t)b*nvec + i];
            lab[0]=(int)v.x; lab[1]=(int)v.y; lab[2]=(int)v.z; lab[3]=(int)v.w;
        } else {
            const int4 v = ((const int4*)labels)[(size_t)b*nvec + i];
            lab[0]=v.x; lab[1]=v.y; lab[2]=v.z; lab[3]=v.w;
        }
#pragma unroll
        for (int p = 0; p < 4; p++) {
            float m[K];
#pragma unroll
            for (int k = 0; k < K; k++) m[k] = (lab[p] == k) ? 1.0f : 0.0f;
            float dist2 = 0.f;
#pragma unroll
            for (int d = 0; d < D; d++) {
                float mu = 0.f;
#pragma unroll
                for (int k = 0; k < K; k++) mu = fmaf(m[k], mean[k][d], mu);
                float tdf = f4c(x[d], p) - mu;
                dist2 = fmaf(tdf, tdf, dist2);
            }
            float dd = sqrtf(dist2);
            float h  = fmaxf(dd - DELTA_V, 0.f);
            float h2 = h*h;
#pragma unroll
            for (int k = 0; k < K; k++) accv[k] = fmaf(m[k], h2, accv[k]);
        }
    }

#pragma unroll
    for (int k = 0; k < K; k++) {
        float v = accv[k];
#pragma unroll
        for (int o = 16; o; o >>= 1) v += __shfl_xor_sync(0xffffffffu, v, o);
        accv[k] = v;
    }
    __shared__ float red[K];
    if (threadIdx.x < K) red[threadIdx.x] = 0.f;
    __syncthreads();
    if ((threadIdx.x & 31) == 0) {
#pragma unroll
        for (int k = 0; k < K; k++) atomicAdd(&red[k], accv[k]);
    }
    __syncthreads();
    if (threadIdx.x < K) atomicAdd(&gvar[b*K + threadIdx.x], red[threadIdx.x]);
}

// ---------------- final combine ---------------------------------------------
__global__ void fin_kernel(float* __restrict__ out) {
    if (threadIdx.x == 0) {
        float bl = 0.f;
        for (int b = 0; b < NB; b++) {
            float lv = 0.f;
            for (int k = 0; k < KB; k++)
                lv += g_bin_var[b][k] / g_bin_acc[b][k*(DB+1)+DB];
            bl += lv / (float)KB + g_bin_rest[b];
        }
        out[0] = bl / (float)NB;
        float il = 0.f;
        for (int b = 0; b < NB; b++) {
            float lv = 0.f;
            for (int k = 0; k < KI; k++)
                lv += g_inst_var[b][k] / g_inst_acc[b][k*(DI+1)+DI];
            il += lv / (float)KI + g_inst_rest[b];
        }
        out[1] = il / (float)NB;
    }
}

// ---------------- launch -----------------------------------------------------
extern "C" void kernel_launch(void* const* d_in, const int* in_sizes, int n_in,
                              void* d_out, int out_size) {
    const float* bin_logits  = (const float*)d_in[0];
    const void*  bin_labels  = d_in[1];
    const float* inst_logits = (const float*)d_in[2];
    const void*  inst_labels = d_in[3];
    float* out = (float*)d_out;

    const int MN = in_sizes[1] / NB;   // label element count per batch

    float *p_bin_acc, *p_inst_acc, *p_bin_mean, *p_inst_mean, *p_bin_var, *p_inst_var;
    cudaGetSymbolAddress((void**)&p_bin_acc,  g_bin_acc);
    cudaGetSymbolAddress((void**)&p_inst_acc, g_inst_acc);
    cudaGetSymbolAddress((void**)&p_bin_mean, g_bin_mean);
    cudaGetSymbolAddress((void**)&p_inst_mean,g_inst_mean);
    cudaGetSymbolAddress((void**)&p_bin_var,  g_bin_var);
    cudaGetSymbolAddress((void**)&p_inst_var, g_inst_var);

    const int THREADS = 256;
    const int GX = 256;                 // 1024 CTAs total per pass kernel
    dim3 grid(GX, NB);

    zero_detect_kernel<<<1, 256>>>((const int*)bin_labels, (const int*)inst_labels);
    pass1_kernel<KB, DB><<<grid, THREADS>>>(bin_logits,  bin_labels,  p_bin_acc,  0, MN);
    pass1_kernel<KI, DI><<<grid, THREADS>>>(inst_logits, inst_labels, p_inst_acc, 1, MN);
    mid_kernel<<<1, 32>>>();
    pass2_kernel<KB, DB><<<grid, THREADS>>>(bin_logits,  bin_labels,  p_bin_mean,  p_bin_var,  0, MN);
    pass2_kernel<KI, DI><<<grid, THREADS>>>(inst_logits, inst_labels, p_inst_mean, p_inst_var, 1, MN);
    fin_kernel<<<1, 32>>>(out);
}